// round 3
// baseline (speedup 1.0000x reference)
#include <cuda_runtime.h>
#include <cstdint>

// Problem constants
#define BATCH 32
#define TT 512
#define NINP 128
#define NHID 1024
#define KTOT (NINP + NHID)        // 1152 unified K
#define DT_C 0.042f
#define EPSH 512.0f               // HARMONIC = N_HID * 0.5

// Geometry: 128 CTAs = 32 col-groups x 4 batch-groups, 512 threads (16 warps)
#define NCTA 128
#define COLS 32                   // output columns per CTA (lane = col)
#define BPC  8                    // batches per CTA
#define TPB  512
#define NW   16
#define KSL  (KTOT / NW)          // 72 K-rows per warp (held as 72 weight regs/lane)

#define BTH (BATCH * TT * NHID)   // elements per output tensor

// SMEM (floats)
#define OFF_IN   0                             // in_s[k][8b]
#define SZ_IN    (KTOT * BPC)                  // 9216
#define OFF_RED  (OFF_IN + SZ_IN)              // red[w][b][c]
#define SZ_RED   (NW * BPC * COLS)             // 4096
#define OFF_HYST (OFF_RED + SZ_RED)            // hyst[c][b]
#define SZ_HYST  (COLS * BPC)                  // 256
#define SMEM_FLOATS (OFF_HYST + SZ_HYST)
#define SMEM_BYTES  (SMEM_FLOATS * 4)          // ~54 KB

// ---- device scratch ----
__device__ float g_xT2[4 * TT * NINP * BPC];     // [bg][t][i][8b]   8 MB
__device__ float g_hyT2[2][4 * NHID * BPC];      // [parity][bg][h][8b] 2x128KB
__device__ volatile unsigned g_flags[NCTA];

// packed f32x2 FMA helpers
__device__ __forceinline__ void ffma2(unsigned long long& acc,
                                      unsigned long long w2,
                                      unsigned long long h2) {
    asm("fma.rn.f32x2 %0, %1, %2, %0;" : "+l"(acc) : "l"(w2), "l"(h2));
}
__device__ __forceinline__ unsigned long long pack2(float lo, float hi) {
    unsigned long long r;
    asm("mov.b64 %0, {%1, %2};" : "=l"(r) : "f"(lo), "f"(hi));
    return r;
}
__device__ __forceinline__ void unpack2(unsigned long long v, float& lo, float& hi) {
    asm("mov.b64 {%0, %1}, %2;" : "=f"(lo), "=f"(hi) : "l"(v));
}

// ------------------------------------------------------------------
__global__ void k_init() {
    int idx = blockIdx.x * blockDim.x + threadIdx.x;
    if (idx < NCTA) g_flags[idx] = 0;
    int stride = gridDim.x * blockDim.x;
    for (int i = idx; i < 4 * NHID * BPC; i += stride) g_hyT2[0][i] = 0.0f;
}

__global__ void k_zero(float* __restrict__ p, int n4) {
    int idx = blockIdx.x * blockDim.x + threadIdx.x;
    int stride = gridDim.x * blockDim.x;
    float4 z = make_float4(0.f, 0.f, 0.f, 0.f);
    float4* p4 = reinterpret_cast<float4*>(p);
    for (int i = idx; i < n4; i += stride) p4[i] = z;
}

// x[b][t][i] -> g_xT2[bg][t][i][b&7]
__global__ void k_xpose(const float* __restrict__ x) {
    int idx = blockIdx.x * blockDim.x + threadIdx.x;
    int stride = gridDim.x * blockDim.x;
    const int N = 4 * TT * NINP * BPC;
    for (int o = idx; o < N; o += stride) {
        int blo = o & 7;
        int i = (o >> 3) & (NINP - 1);
        int t = (o >> 10) & (TT - 1);
        int bg = o >> 19;
        g_xT2[o] = x[((size_t)(bg * 8 + blo) * TT + t) * NINP + i];
    }
}

// ------------------------------------------------------------------
// persistent recurrent kernel: 128 CTAs x 512 threads, weights in registers
// ------------------------------------------------------------------
__global__ void __launch_bounds__(TPB, 1) k_recur(
    const float* __restrict__ x2h,    // [NINP][NHID]
    const float* __restrict__ h2h,    // [NHID][NHID]
    const float* __restrict__ gamma,
    const float* __restrict__ eps,
    const float* __restrict__ bias,
    float* __restrict__ out)          // [4][B][T][H]
{
    extern __shared__ float sm[];
    float* in_s = sm + OFF_IN;    // [KTOT][BPC]
    float* red  = sm + OFF_RED;   // [NW][BPC][COLS]
    float* hyst = sm + OFF_HYST;  // [COLS][BPC]

    const int tid  = threadIdx.x;
    const int wid  = tid >> 5;
    const int lane = tid & 31;
    const int cgrp = blockIdx.x >> 2;
    const int bg   = blockIdx.x & 3;
    const int cg0  = cgrp * COLS;
    const int kb   = wid * KSL;

    // --- preload this lane's weight column slice into registers ---
    float wreg[KSL];
#pragma unroll
    for (int j = 0; j < KSL; j++) {
        int k = kb + j;
        wreg[j] = (k < NINP) ? x2h[(size_t)k * NHID + cg0 + lane]
                             : h2h[(size_t)(k - NINP) * NHID + cg0 + lane];
    }

    // --- per-output state (update mapping: tid<256, uc=tid&31, ub=tid>>5) ---
    const int uc = tid & 31;
    const int ub = (tid >> 5) & 7;
    const int hg = cg0 + uc;
    float hy_r = 0.f, hz_r = 0.f;
    float gam = 0.f, epc = 0.f, bi = 0.f;
    if (tid < 256) {
        gam = gamma[hg];
        epc = eps[hg] * EPSH;
        bi  = bias[hg];
    }

    const float* xbase  = g_xT2 + (size_t)bg * (TT * NINP * BPC);
    const unsigned mybid = blockIdx.x;

    for (int t = 0; t < TT; t++) {
        const int p = t & 1;

        // ---- per-warp staging of OWN k-rows (no CTA sync needed) ----
        {
            const int ke = kb + KSL;
            // x segment: rows [kb, min(ke,128))
            if (kb < NINP) {
                int xe = (ke < NINP) ? ke : NINP;
                const float4* src = (const float4*)(xbase + ((size_t)t * NINP + kb) * BPC);
                float4* dst = (float4*)(in_s + kb * BPC);
                int n4 = (xe - kb) * 2;
                for (int i = lane; i < n4; i += 32) dst[i] = __ldg(&src[i]);
            }
            // hy segment: rows [max(kb,128), ke)
            if (ke > NINP) {
                int hb = (kb > NINP) ? kb : NINP;
                const float4* src = (const float4*)(g_hyT2[p]
                                    + (size_t)bg * (NHID * BPC) + (size_t)(hb - NINP) * BPC);
                float4* dst = (float4*)(in_s + hb * BPC);
                int n4 = (ke - hb) * 2;
                for (int i = lane; i < n4; i += 32) {
                    float4 v = __ldcg(&src[i]);   // L1-bypass: cross-CTA coherent
                    dst[i] = v;
                }
            }
            __syncwarp();
        }

        // ---- GEMM slice: 72 k-rows, lane = col, 8 batches packed in 4 acc2 x2 ----
        unsigned long long acc2[8];
#pragma unroll
        for (int i = 0; i < 8; i++) acc2[i] = 0ull;

#pragma unroll
        for (int j = 0; j < KSL; j++) {
            const ulonglong2* hr = (const ulonglong2*)(in_s + (size_t)(kb + j) * BPC);
            ulonglong2 ha = hr[0];   // batches 0..3 (broadcast)
            ulonglong2 hb2 = hr[1];  // batches 4..7
            unsigned long long w2 = pack2(wreg[j], wreg[j]);
            const int a = (j & 1) * 4;
            ffma2(acc2[a + 0], w2, ha.x);
            ffma2(acc2[a + 1], w2, ha.y);
            ffma2(acc2[a + 2], w2, hb2.x);
            ffma2(acc2[a + 3], w2, hb2.y);
        }

        // ---- write partials: red[wid][b][lane] ----
#pragma unroll
        for (int i = 0; i < 4; i++) {
            float lo0, hi0, lo1, hi1;
            unpack2(acc2[i], lo0, hi0);
            unpack2(acc2[i + 4], lo1, hi1);
            red[(wid * BPC + 2 * i) * COLS + lane]     = lo0 + lo1;
            red[(wid * BPC + 2 * i + 1) * COLS + lane] = hi0 + hi1;
        }
        __syncthreads();

        // ---- update: threads 0..255 own (uc, ub) ----
        if (tid < 256) {
            float pre = bi;
#pragma unroll
            for (int w = 0; w < NW; w++)
                pre += red[(w * BPC + ub) * COLS + uc];
            float drive = tanhf(pre);
            hz_r += DT_C * (drive - gam * hy_r - epc * hz_r);
            hy_r += DT_C * hz_r;

            const size_t obase = (size_t)(bg * BPC + ub) * (TT * NHID) + (size_t)t * NHID + hg;
            out[obase]       = hy_r;
            out[obase + BTH] = hz_r;
            hyst[uc * BPC + ub] = hy_r;
        }
        __syncthreads();

        // ---- hy writeback: 64 threads x float4, fully contiguous 1KB ----
        if (tid < 64) {
            const float4* hs4 = (const float4*)hyst;
            float4 v = hs4[tid];
            float4* dst = (float4*)(g_hyT2[p ^ 1] + (size_t)bg * (NHID * BPC)
                                    + (size_t)cg0 * BPC) + tid;
            __stcg(dst, v);
        }
        __syncthreads();

        // ---- grid barrier: flag array (no atomic serialization) ----
        if (tid == 0) {
            __threadfence();
            g_flags[mybid] = (unsigned)(t + 1);
        }
        if (tid < NCTA) {
            const unsigned want = (unsigned)(t + 1);
            if (g_flags[tid] < want) {
                while (g_flags[tid] < want) __nanosleep(32);
            }
        }
        __threadfence();
        __syncthreads();
    }
}

// ------------------------------------------------------------------
extern "C" void kernel_launch(void* const* d_in, const int* in_sizes, int n_in,
                              void* d_out, int out_size) {
    const float* x     = (const float*)d_in[0];
    const float* x2h   = (const float*)d_in[1];
    const float* h2h   = (const float*)d_in[2];
    const float* gamma = (const float*)d_in[3];
    const float* eps   = (const float*)d_in[4];
    const float* bias  = (const float*)d_in[5];
    float* out = (float*)d_out;

    static bool attr_set = false;
    if (!attr_set) {
        cudaFuncSetAttribute(k_recur, cudaFuncAttributeMaxDynamicSharedMemorySize, SMEM_BYTES);
        attr_set = true;
    }

    k_init<<<64, 256>>>();
    k_xpose<<<512, 256>>>(x);
    // u and spike outputs are identically zero (u never leaves 0)
    k_zero<<<2048, 256>>>(out + (size_t)2 * BTH, (2 * BTH) / 4);
    k_recur<<<NCTA, TPB, SMEM_BYTES>>>(x2h, h2h, gamma, eps, bias, out);
}

// round 4
// speedup vs baseline: 1.0147x; 1.0147x over previous
#include <cuda_runtime.h>
#include <cstdint>

// Problem constants
#define BATCH 32
#define TT 512
#define NINP 128
#define NHID 1024
#define KTOT (NINP + NHID)        // 1152 unified K
#define DT_C 0.042f
#define EPSH 512.0f               // HARMONIC = N_HID * 0.5

// Geometry: 128 CTAs = 32 col-groups x 4 batch-groups, 512 threads (16 warps)
#define NCTA 128
#define COLS 32
#define BPC  8
#define TPB  512
#define NW   16
#define KSL  (KTOT / NW)          // 72 k-rows per warp
#define WS2  36                   // weight row stride (floats): 36 % 32 == 4 -> conflict-free

#define BTH (BATCH * TT * NHID)

// SMEM layout (floats)
#define OFF_W    0
#define SZ_W     (KTOT * WS2)                  // 41472
#define OFF_IN   (OFF_W + SZ_W)                // in_s[k][8b]
#define SZ_IN    (KTOT * BPC)                  // 9216
#define OFF_RED  (OFF_IN + SZ_IN)              // red[w][b][c]
#define SZ_RED   (NW * BPC * COLS)             // 4096
#define OFF_HYST (OFF_RED + SZ_RED)            // hyst[c][b]
#define SZ_HYST  (COLS * BPC)                  // 256
#define SMEM_FLOATS (OFF_HYST + SZ_HYST)
#define SMEM_BYTES  (SMEM_FLOATS * 4)          // 220,160 B

// ---- device scratch ----
__device__ float g_xT2[4 * TT * NINP * BPC];   // [bg][t][i][8b]
__device__ float g_hyT2[2][4 * NHID * BPC];    // [parity][bg][h][8b]
__device__ volatile unsigned g_flags[NCTA];

// packed f32x2 helpers
__device__ __forceinline__ void ffma2(unsigned long long& acc,
                                      unsigned long long a,
                                      unsigned long long b) {
    asm("fma.rn.f32x2 %0, %1, %2, %0;" : "+l"(acc) : "l"(a), "l"(b));
}
__device__ __forceinline__ unsigned long long add2(unsigned long long a,
                                                   unsigned long long b) {
    unsigned long long r;
    asm("add.rn.f32x2 %0, %1, %2;" : "=l"(r) : "l"(a), "l"(b));
    return r;
}
__device__ __forceinline__ unsigned long long pack2(float lo, float hi) {
    unsigned long long r;
    asm("mov.b64 %0, {%1, %2};" : "=l"(r) : "f"(lo), "f"(hi));
    return r;
}
__device__ __forceinline__ void unpack2(unsigned long long v, float& lo, float& hi) {
    asm("mov.b64 {%0, %1}, %2;" : "=f"(lo), "=f"(hi) : "l"(v));
}

// ------------------------------------------------------------------
__global__ void k_init() {
    int idx = blockIdx.x * blockDim.x + threadIdx.x;
    if (idx < NCTA) g_flags[idx] = 0;
    int stride = gridDim.x * blockDim.x;
    for (int i = idx; i < 4 * NHID * BPC; i += stride) g_hyT2[0][i] = 0.0f;
}

__global__ void k_zero(float* __restrict__ p, int n4) {
    int idx = blockIdx.x * blockDim.x + threadIdx.x;
    int stride = gridDim.x * blockDim.x;
    float4 z = make_float4(0.f, 0.f, 0.f, 0.f);
    float4* p4 = reinterpret_cast<float4*>(p);
    for (int i = idx; i < n4; i += stride) p4[i] = z;
}

// x[b][t][i] -> g_xT2[bg][t][i][b&7]
__global__ void k_xpose(const float* __restrict__ x) {
    int idx = blockIdx.x * blockDim.x + threadIdx.x;
    int stride = gridDim.x * blockDim.x;
    const int N = 4 * TT * NINP * BPC;
    for (int o = idx; o < N; o += stride) {
        int blo = o & 7;
        int i = (o >> 3) & (NINP - 1);
        int t = (o >> 10) & (TT - 1);
        int bg = o >> 19;
        g_xT2[o] = x[((size_t)(bg * 8 + blo) * TT + t) * NINP + i];
    }
}

// ------------------------------------------------------------------
// persistent recurrent kernel: 128 CTAs x 512 threads
// GEMM mapping: lane = (kq in [0,8)) * 4 + (cs in [0,4));
//   per inner iteration a warp covers 8 k-rows for all 32 cols;
//   lane accumulates (8 cols {cs,cs+4,...}) x (8 batches).
// ------------------------------------------------------------------
__global__ void __launch_bounds__(TPB, 1) k_recur(
    const float* __restrict__ x2h,
    const float* __restrict__ h2h,
    const float* __restrict__ gamma,
    const float* __restrict__ eps,
    const float* __restrict__ bias,
    float* __restrict__ out)
{
    extern __shared__ float sm[];
    float* w2_s = sm + OFF_W;     // [KTOT][WS2] k-major
    float* in_s = sm + OFF_IN;    // [KTOT][BPC]
    float* red  = sm + OFF_RED;   // [NW][BPC][COLS]
    float* hyst = sm + OFF_HYST;  // [COLS][BPC]

    const int tid  = threadIdx.x;
    const int wid  = tid >> 5;
    const int lane = tid & 31;
    const int kq   = lane >> 2;   // 0..7
    const int cs   = lane & 3;    // 0..3
    const int cgrp = blockIdx.x >> 2;
    const int bg   = blockIdx.x & 3;
    const int cg0  = cgrp * COLS;
    const int b0g  = bg * BPC;
    const int kb   = wid * KSL;

    // --- weights into SMEM, k-major with stride 36 ---
    for (int idx = tid; idx < KTOT * COLS; idx += TPB) {
        int k = idx >> 5;
        int c = idx & 31;
        float v = (k < NINP) ? x2h[(size_t)k * NHID + cg0 + c]
                             : h2h[(size_t)(k - NINP) * NHID + cg0 + c];
        w2_s[k * WS2 + c] = v;
    }

    // --- per-output state (update mapping: tid<256) ---
    const int uc = tid & 31;
    const int ub = (tid >> 5) & 7;
    const int hg = cg0 + uc;
    float hy_r = 0.f, hz_r = 0.f;
    float gam = 0.f, epc = 0.f, bi = 0.f;
    if (tid < 256) {
        gam = gamma[hg];
        epc = eps[hg] * EPSH;
        bi  = bias[hg];
    }

    const float* xbase = g_xT2 + (size_t)bg * (TT * NINP * BPC);
    __syncthreads();

    for (int t = 0; t < TT; t++) {
        const int p = t & 1;

        // ---- per-warp staging of OWN 72 k-rows (warp-private in_s region) ----
        {
            const int ke = kb + KSL;
            if (kb < NINP) {
                int xe = (ke < NINP) ? ke : NINP;
                const float4* src = (const float4*)(xbase + ((size_t)t * NINP + kb) * BPC);
                float4* dst = (float4*)(in_s + kb * BPC);
                int n4 = (xe - kb) * 2;
                for (int i = lane; i < n4; i += 32) dst[i] = __ldg(&src[i]);
            }
            if (ke > NINP) {
                int hb = (kb > NINP) ? kb : NINP;
                const float4* src = (const float4*)(g_hyT2[p]
                                    + (size_t)bg * (NHID * BPC) + (size_t)(hb - NINP) * BPC);
                float4* dst = (float4*)(in_s + hb * BPC);
                int n4 = (ke - hb) * 2;
                for (int i = lane; i < n4; i += 32) dst[i] = __ldcg(&src[i]);
            }
            __syncwarp();
        }

        // ---- GEMM: 9 iterations x 8 k-rows; acc[j][m]: j = col offset, m = batch pair ----
        unsigned long long acc[8][4];
#pragma unroll
        for (int j = 0; j < 8; j++)
#pragma unroll
            for (int m = 0; m < 4; m++) acc[j][m] = 0ull;

#pragma unroll
        for (int it = 0; it < KSL / 8; it++) {
            const int k = kb + it * 8 + kq;               // this lane's k-row
            const ulonglong2* hr = (const ulonglong2*)(in_s + (size_t)k * BPC);
            ulonglong2 ha = hr[0];                        // batches 0..3
            ulonglong2 hb2 = hr[1];                       // batches 4..7
            const float* wrow = w2_s + (size_t)k * WS2 + cs;
#pragma unroll
            for (int j = 0; j < 8; j++) {
                unsigned long long w2 = pack2(wrow[4 * j], wrow[4 * j]);
                ffma2(acc[j][0], w2, ha.x);
                ffma2(acc[j][1], w2, ha.y);
                ffma2(acc[j][2], w2, hb2.x);
                ffma2(acc[j][3], w2, hb2.y);
            }
        }

        // ---- halving shfl butterfly over kq (lane bits 4,3,2) ----
        // After 3 rounds each lane holds 8 floats (batches) for col = cs + 4*kq = lane.
        unsigned long long* A = &acc[0][0];   // 32 u64, j-major
#pragma unroll
        for (int r = 0; r < 3; r++) {
            const int msk = 16 >> r;          // 16, 8, 4
            const int n   = 16 >> r;          // u64 kept this round
            const bool up = (lane & msk) != 0;
#pragma unroll
            for (int i = 0; i < n; i++) {
                unsigned long long mine  = up ? A[i + n] : A[i];
                unsigned long long other = up ? A[i]     : A[i + n];
                unsigned long long recv  = __shfl_xor_sync(0xffffffffu, other, msk);
                A[i] = add2(mine, recv);
            }
        }

        // ---- store per-warp partials: red[wid][b][lane] ----
#pragma unroll
        for (int m = 0; m < 4; m++) {
            float lo, hi;
            unpack2(A[m], lo, hi);
            red[(wid * BPC + 2 * m) * COLS + lane]     = lo;
            red[(wid * BPC + 2 * m + 1) * COLS + lane] = hi;
        }
        __syncthreads();

        // ---- update: threads 0..255 own (uc, ub) ----
        if (tid < 256) {
            float pre = bi;
#pragma unroll
            for (int w = 0; w < NW; w++)
                pre += red[(w * BPC + ub) * COLS + uc];
            float drive = tanhf(pre);
            hz_r += DT_C * (drive - gam * hy_r - epc * hz_r);
            hy_r += DT_C * hz_r;

            const size_t obase = (size_t)(b0g + ub) * (TT * NHID) + (size_t)t * NHID + hg;
            out[obase]       = hy_r;
            out[obase + BTH] = hz_r;
            hyst[uc * BPC + ub] = hy_r;
        }
        __syncthreads();

        // ---- hy writeback: 64 threads x float4 contiguous ----
        if (tid < 64) {
            const float4* hs4 = (const float4*)hyst;
            float4 v = hs4[tid];
            float4* dst = (float4*)(g_hyT2[p ^ 1] + (size_t)bg * (NHID * BPC)
                                    + (size_t)cg0 * BPC) + tid;
            __stcg(dst, v);
        }
        __syncthreads();

        // ---- grid barrier: flag array, fences only where needed ----
        if (tid == 0) {
            __threadfence();
            g_flags[blockIdx.x] = (unsigned)(t + 1);
        }
        if (tid < NCTA) {
            const unsigned want = (unsigned)(t + 1);
            while (g_flags[tid] < want) __nanosleep(16);
            __threadfence();   // acquire (only warps 0-3)
        }
        __syncthreads();
    }
}

// ------------------------------------------------------------------
extern "C" void kernel_launch(void* const* d_in, const int* in_sizes, int n_in,
                              void* d_out, int out_size) {
    const float* x     = (const float*)d_in[0];
    const float* x2h   = (const float*)d_in[1];
    const float* h2h   = (const float*)d_in[2];
    const float* gamma = (const float*)d_in[3];
    const float* eps   = (const float*)d_in[4];
    const float* bias  = (const float*)d_in[5];
    float* out = (float*)d_out;

    static bool attr_set = false;
    if (!attr_set) {
        cudaFuncSetAttribute(k_recur, cudaFuncAttributeMaxDynamicSharedMemorySize, SMEM_BYTES);
        attr_set = true;
    }

    k_init<<<64, 256>>>();
    k_xpose<<<512, 256>>>(x);
    // u and spike outputs are identically zero (u never leaves 0)
    k_zero<<<2048, 256>>>(out + (size_t)2 * BTH, (2 * BTH) / 4);
    k_recur<<<NCTA, TPB, SMEM_BYTES>>>(x2h, h2h, gamma, eps, bias, out);
}